// round 14
// baseline (speedup 1.0000x reference)
#include <cuda_runtime.h>
#include <cuda_fp16.h>
#include <stdint.h>
#include <math.h>

#define Bb 256
#define Tt 256
#define Cc 384
#define Hh 64

// Intermediates: fp16 projections (Q pre-scaled by C^-0.5), V also transposed.
__device__ __half  g_q[Bb * Tt * Hh];
__device__ __half  g_k[Bb * Tt * Hh];
__device__ __half  g_v[Bb * Tt * Hh];
__device__ __half  g_vT[Bb * Hh * Tt];          // [b][h][t]
__device__ uint32_t g_wt[12 * 3072];            // fp16 B-fragments: [ch][ntg24][ks2][lane32][j2]

// ---------------- helpers ----------------
__device__ __forceinline__ uint32_t pkhalf2(float lo, float hi) {
    uint32_t d;
    asm("cvt.rn.f16x2.f32 %0, %1, %2;" : "=r"(d) : "f"(hi), "f"(lo));
    return d;
}
__device__ __forceinline__ uint32_t smaddr(const void* p) {
    return (uint32_t)__cvta_generic_to_shared(p);
}
__device__ __forceinline__ void cpa16(uint32_t d, const void* s) {
    asm volatile("cp.async.cg.shared.global [%0], [%1], 16;\n" :: "r"(d), "l"(s));
}
__device__ __forceinline__ void cp_commit() { asm volatile("cp.async.commit_group;\n"); }
__device__ __forceinline__ void cp_wait0()  { asm volatile("cp.async.wait_group 0;\n" ::: "memory"); }

// m16n8k16 fp16 mma, fp32 accum
__device__ __forceinline__ void mma16(float c[4], const uint32_t a[4], uint32_t b0, uint32_t b1) {
    asm volatile(
        "mma.sync.aligned.m16n8k16.row.col.f32.f16.f16.f32 "
        "{%0,%1,%2,%3},{%4,%5,%6,%7},{%8,%9},{%0,%1,%2,%3};\n"
        : "+f"(c[0]), "+f"(c[1]), "+f"(c[2]), "+f"(c[3])
        : "r"(a[0]), "r"(a[1]), "r"(a[2]), "r"(a[3]), "r"(b0), "r"(b1));
}

// ---------------------------------------------------------------------------
// Kernel 0: weights -> fp16 B-fragments.
//   g_wt[(((ch*24+ntg)*2+ks)*32+lane)*2+j] = half2(W[k][n], W[k+1][n]),
//   n = ntg*8+gid, k = ch*32 + ks*16 + 2*tig + 8*j.
// ---------------------------------------------------------------------------
__global__ __launch_bounds__(512) void prep_w(
    const float* __restrict__ Wq, const float* __restrict__ Wk, const float* __restrict__ Wv)
{
    int idx = blockIdx.x * 512 + threadIdx.x;   // 72 blocks -> 36864
    int j    = idx & 1;
    int lane = (idx >> 1) & 31;
    int ks   = (idx >> 6) & 1;
    int t    = idx >> 7;
    int ntg  = t % 24, ch = t / 24;
    int gid  = lane >> 2, tig = lane & 3;

    int n = ntg * 8 + gid;
    const float* W = (n < 64) ? Wq : (n < 128) ? Wk : Wv;
    int nc = n & 63;
    int k  = ch * 32 + ks * 16 + 2 * tig + 8 * j;

    g_wt[idx] = pkhalf2(W[k * Hh + nc], W[(k + 1) * Hh + nc]);
}

// ---------------------------------------------------------------------------
// Kernel 1: fused QKV projection, fp16 m16n8k16 (R11 winner).
//   256 threads = 8 warps (4m x 2n), warp tile 32x96, block 128x192,
//   K-chunk 32 (2 k16 steps), double-buffered cp.async. 3 CTAs/SM.
// Smem: Xs 2*128*36 fp32 (raw x) | Wb 2*3072 u32 fragments = 61440 B
// ---------------------------------------------------------------------------
__global__ __launch_bounds__(256, 3) void qkv_mma(const float* __restrict__ x)
{
    extern __shared__ uint32_t sm[];
    float*    Xs = (float*)sm;            // 2 * 128*36
    uint32_t* Wb = sm + 2 * 128 * 36;     // 2 * 3072

    const int tid  = threadIdx.x;
    const int lane = tid & 31;
    const int wid  = tid >> 5;
    const int gid  = lane >> 2;
    const int tig  = lane & 3;
    const int wm   = wid & 3;           // rows wm*32
    const int wn   = wid >> 2;          // cols wn*96
    const int row0 = blockIdx.x * 128;

    auto issue = [&](int ch) {
        float*    Xb = Xs + (ch & 1) * (128 * 36);
        uint32_t* Bq = Wb + (ch & 1) * 3072;
        int kk = ch * 32;
        #pragma unroll
        for (int i = 0; i < 4; i++) {
            int idx = tid + i * 256;
            int r = idx >> 3, c4 = (idx & 7) * 4;
            cpa16(smaddr(&Xb[r * 36 + c4]), &x[(size_t)(row0 + r) * Cc + kk + c4]);
        }
        #pragma unroll
        for (int i = 0; i < 3; i++) {
            int idx = tid + i * 256;    // 768 granules of 16B
            cpa16(smaddr(&Bq[idx * 4]), &g_wt[(size_t)ch * 3072 + idx * 4]);
        }
        cp_commit();
    };

    float acc[2][12][4] = {};
    issue(0);

    for (int ch = 0; ch < 12; ch++) {
        cp_wait0();
        __syncthreads();
        if (ch < 11) issue(ch + 1);

        const float*    Xb = Xs + (ch & 1) * (128 * 36);
        const uint32_t* Bq = Wb + (ch & 1) * 3072;

        #pragma unroll
        for (int ks = 0; ks < 2; ks++) {
            // A fragments (fp32 -> fp16 pack in registers)
            uint32_t a[2][4];
            #pragma unroll
            for (int mt = 0; mt < 2; mt++) {
                int r = wm * 32 + mt * 16;
                float2 v0 = *(const float2*)&Xb[(r + gid) * 36 + ks * 16 + 2 * tig];
                float2 v1 = *(const float2*)&Xb[(r + gid + 8) * 36 + ks * 16 + 2 * tig];
                float2 v2 = *(const float2*)&Xb[(r + gid) * 36 + ks * 16 + 2 * tig + 8];
                float2 v3 = *(const float2*)&Xb[(r + gid + 8) * 36 + ks * 16 + 2 * tig + 8];
                a[mt][0] = pkhalf2(v0.x, v0.y);
                a[mt][1] = pkhalf2(v1.x, v1.y);
                a[mt][2] = pkhalf2(v2.x, v2.y);
                a[mt][3] = pkhalf2(v3.x, v3.y);
            }
            // B fragments, 2 halves of 6 n-tiles
            #pragma unroll
            for (int h = 0; h < 2; h++) {
                uint2 Bv[6];
                #pragma unroll
                for (int t = 0; t < 6; t++) {
                    int ntl = h * 6 + t;
                    Bv[t] = *(const uint2*)&Bq[(((wn * 12 + ntl) * 2 + ks) * 32 + lane) * 2];
                }
                #pragma unroll
                for (int mt = 0; mt < 2; mt++)
                    #pragma unroll
                    for (int t = 0; t < 6; t++)
                        mma16(acc[mt][h * 6 + t], a[mt], Bv[t].x, Bv[t].y);
            }
        }
    }

    // Epilogue: fp16 stores; Q pre-scaled by C^-0.5
    const float scale = rsqrtf((float)Cc);
    #pragma unroll
    for (int mt = 0; mt < 2; mt++) {
        #pragma unroll
        for (int ntl = 0; ntl < 12; ntl++) {
            int n = wn * 96 + ntl * 8 + tig * 2;
            __half* outp = (n < 64) ? g_q : (n < 128) ? g_k : g_v;
            float sc = (n < 64) ? scale : 1.0f;
            int ncu = (n & 63) >> 1;
            int r = row0 + wm * 32 + mt * 16 + gid;
            ((uint32_t*)outp)[r * 32 + ncu] =
                pkhalf2(acc[mt][ntl][0] * sc, acc[mt][ntl][1] * sc);
            ((uint32_t*)outp)[(r + 8) * 32 + ncu] =
                pkhalf2(acc[mt][ntl][2] * sc, acc[mt][ntl][3] * sc);
        }
    }
}

// ---------------------------------------------------------------------------
// Kernel 1b: transpose V per batch: g_v[b][t][h] -> g_vT[b][h][t].
// ---------------------------------------------------------------------------
__global__ __launch_bounds__(256) void vtrans()
{
    __shared__ __half ts[64][260];
    const int b = blockIdx.x;
    const int tid = threadIdx.x;

    #pragma unroll
    for (int i = 0; i < 32; i++) {
        int idx = tid + i * 256;          // 8192 u32 of g_v slice
        int tok = idx >> 5, hp = idx & 31;
        uint32_t v = ((const uint32_t*)g_v)[(size_t)(b * Tt + tok) * 32 + hp];
        ts[hp * 2 + 0][tok] = __ushort_as_half((unsigned short)(v & 0xFFFF));
        ts[hp * 2 + 1][tok] = __ushort_as_half((unsigned short)(v >> 16));
    }
    __syncthreads();
    #pragma unroll
    for (int i = 0; i < 32; i++) {
        int idx = tid + i * 256;
        int h = idx >> 7, tp = idx & 127;
        ((uint32_t*)g_vT)[(size_t)(b * Hh + h) * 128 + tp] = *(uint32_t*)&ts[h][tp * 2];
    }
}

// ---------------------------------------------------------------------------
// Kernel 2: flash-attention, fp16 m16n8k16 (R11 winner), now 4 CTAs/SM.
// Smem (u32): Q 128*36 | K 2*64*36 | VT 2*64*36 = 55296 B
// ---------------------------------------------------------------------------
__global__ __launch_bounds__(256, 4) void attn_flash(float* __restrict__ out)
{
    extern __shared__ uint32_t sm[];
    uint32_t* Qs = sm;                 // 128*36
    uint32_t* Kb = sm + 128 * 36;      // 2 * 64*36
    uint32_t* Vb = Kb + 2 * 64 * 36;   // 2 * 64*36

    const int tid  = threadIdx.x;
    const int lane = tid & 31;
    const int wid  = tid >> 5;
    const int gid  = lane >> 2;
    const int tig  = lane & 3;
    const int qt   = 1 - blockIdx.x;    // heavy blocks first
    const int b    = blockIdx.y;
    const int q0   = qt * 128;
    const int r0   = wid * 16;
    const int lastT = 2 * qt + 1;
    const int dtile = (q0 + r0) >> 6;

    // Prologue: Q + K0 + V0
    #pragma unroll
    for (int i = 0; i < 4; i++) {
        int idx = tid + i * 256;
        int r = idx >> 3, gq = (idx & 7) * 4;
        cpa16(smaddr(&Qs[r * 36 + gq]), &g_q[(size_t)(b * Tt + q0 + r) * Hh + gq * 2]);
    }
    #pragma unroll
    for (int i = 0; i < 2; i++) {
        int idx = tid + i * 256;
        int r = idx >> 3, gq = (idx & 7) * 4;
        cpa16(smaddr(&Kb[r * 36 + gq]), &g_k[(size_t)(b * Tt + r) * Hh + gq * 2]);
        cpa16(smaddr(&Vb[r * 36 + gq]), &g_vT[(size_t)(b * Hh + r) * Tt + gq * 2]);
    }
    cp_commit();
    cp_wait0();
    __syncthreads();

    // Q fragments -> registers (16 u32)
    uint32_t Qa[4][4];
    #pragma unroll
    for (int ks = 0; ks < 4; ks++) {
        Qa[ks][0] = Qs[(r0 + gid) * 36 + 8 * ks + tig];
        Qa[ks][1] = Qs[(r0 + gid + 8) * 36 + 8 * ks + tig];
        Qa[ks][2] = Qs[(r0 + gid) * 36 + 8 * ks + tig + 4];
        Qa[ks][3] = Qs[(r0 + gid + 8) * 36 + 8 * ks + tig + 4];
    }

    float o[8][4] = {};
    float m0 = -1e30f, m1 = -1e30f, l0 = 0.f, l1 = 0.f;

    for (int jt = 0; jt <= lastT; jt++) {
        if (jt < lastT) {
            uint32_t* Kn = Kb + ((jt + 1) & 1) * (64 * 36);
            uint32_t* Vn = Vb + ((jt + 1) & 1) * (64 * 36);
            #pragma unroll
            for (int i = 0; i < 2; i++) {
                int idx = tid + i * 256;
                int r = idx >> 3, gq = (idx & 7) * 4;
                cpa16(smaddr(&Kn[r * 36 + gq]),
                      &g_k[(size_t)(b * Tt + (jt + 1) * 64 + r) * Hh + gq * 2]);
                cpa16(smaddr(&Vn[r * 36 + gq]),
                      &g_vT[(size_t)(b * Hh + r) * Tt + (jt + 1) * 64 + gq * 2]);
            }
            cp_commit();
        }

        if (jt <= dtile) {
            const uint32_t* K = Kb + (jt & 1) * (64 * 36);
            const uint32_t* V = Vb + (jt & 1) * (64 * 36);

            // ---- S = Q K^T : 16 rows x 64 keys ----
            float c4[8][4] = {};
            #pragma unroll
            for (int ks = 0; ks < 4; ks++) {
                #pragma unroll
                for (int nt = 0; nt < 8; nt++) {
                    int n = nt * 8 + gid;
                    uint32_t b0 = K[n * 36 + 8 * ks + tig];
                    uint32_t b1 = K[n * 36 + 8 * ks + tig + 4];
                    mma16(c4[nt], Qa[ks], b0, b1);
                }
            }

            if (jt == dtile) {
                int qg0 = q0 + r0 + gid, qg1 = qg0 + 8;
                #pragma unroll
                for (int nt = 0; nt < 8; nt++) {
                    int kg = jt * 64 + nt * 8 + tig * 2;
                    if (kg     > qg0) c4[nt][0] = -1e30f;
                    if (kg + 1 > qg0) c4[nt][1] = -1e30f;
                    if (kg     > qg1) c4[nt][2] = -1e30f;
                    if (kg + 1 > qg1) c4[nt][3] = -1e30f;
                }
            }

            // ---- online softmax ----
            float mx0 = -1e30f, mx1 = -1e30f;
            #pragma unroll
            for (int nt = 0; nt < 8; nt++) {
                mx0 = fmaxf(mx0, fmaxf(c4[nt][0], c4[nt][1]));
                mx1 = fmaxf(mx1, fmaxf(c4[nt][2], c4[nt][3]));
            }
            mx0 = fmaxf(mx0, __shfl_xor_sync(0xffffffffu, mx0, 1));
            mx0 = fmaxf(mx0, __shfl_xor_sync(0xffffffffu, mx0, 2));
            mx1 = fmaxf(mx1, __shfl_xor_sync(0xffffffffu, mx1, 1));
            mx1 = fmaxf(mx1, __shfl_xor_sync(0xffffffffu, mx1, 2));

            float m0n = fmaxf(m0, mx0), m1n = fmaxf(m1, mx1);
            float a0 = __expf(m0 - m0n), a1 = __expf(m1 - m1n);
            m0 = m0n; m1 = m1n;

            float s0 = 0.f, s1 = 0.f;
            #pragma unroll
            for (int nt = 0; nt < 8; nt++) {
                c4[nt][0] = __expf(c4[nt][0] - m0n);
                c4[nt][1] = __expf(c4[nt][1] - m0n);
                c4[nt][2] = __expf(c4[nt][2] - m1n);
                c4[nt][3] = __expf(c4[nt][3] - m1n);
                s0 += c4[nt][0] + c4[nt][1];
                s1 += c4[nt][2] + c4[nt][3];
            }
            s0 += __shfl_xor_sync(0xffffffffu, s0, 1);
            s0 += __shfl_xor_sync(0xffffffffu, s0, 2);
            s1 += __shfl_xor_sync(0xffffffffu, s1, 1);
            s1 += __shfl_xor_sync(0xffffffffu, s1, 2);
            l0 = l0 * a0 + s0;
            l1 = l1 * a1 + s1;

            #pragma unroll
            for (int nt = 0; nt < 8; nt++) {
                o[nt][0] *= a0; o[nt][1] *= a0;
                o[nt][2] *= a1; o[nt][3] *= a1;
            }

            // ---- O += P V : P packs straight into A fragments ----
            #pragma unroll
            for (int j = 0; j < 4; j++) {
                uint32_t a[4];
                a[0] = pkhalf2(c4[2 * j][0],     c4[2 * j][1]);
                a[1] = pkhalf2(c4[2 * j][2],     c4[2 * j][3]);
                a[2] = pkhalf2(c4[2 * j + 1][0], c4[2 * j + 1][1]);
                a[3] = pkhalf2(c4[2 * j + 1][2], c4[2 * j + 1][3]);
                #pragma unroll
                for (int nt = 0; nt < 8; nt++) {
                    int n = nt * 8 + gid;                  // h column
                    uint32_t b0 = V[n * 36 + 8 * j + tig];
                    uint32_t b1 = V[n * 36 + 8 * j + tig + 4];
                    mma16(o[nt], a, b0, b1);
                }
            }
        }

        if (jt < lastT) {
            cp_wait0();
            __syncthreads();
        }
    }

    // ---- normalize and store fp32 ----
    float i0 = 1.f / l0, i1 = 1.f / l1;
    int row = b * Tt + q0 + r0 + gid;
    #pragma unroll
    for (int nt = 0; nt < 8; nt++) {
        int col = nt * 8 + tig * 2;
        *(float2*)&out[(size_t)row * Hh + col]       = make_float2(o[nt][0] * i0, o[nt][1] * i0);
        *(float2*)&out[(size_t)(row + 8) * Hh + col] = make_float2(o[nt][2] * i1, o[nt][3] * i1);
    }
}

// ---------------------------------------------------------------------------
extern "C" void kernel_launch(void* const* d_in, const int* in_sizes, int n_in,
                              void* d_out, int out_size)
{
    const float* x  = (const float*)d_in[0];
    const float* Wq = (const float*)d_in[1];
    const float* Wk = (const float*)d_in[2];
    const float* Wv = (const float*)d_in[3];
    float* out = (float*)d_out;

    static const int kQkvSmem  = (2 * 128 * 36 + 2 * 3072) * (int)sizeof(uint32_t);   // 61440
    static const int kAttnSmem = (128 * 36 + 4 * 64 * 36) * (int)sizeof(uint32_t);    // 55296
    cudaFuncSetAttribute(qkv_mma, cudaFuncAttributeMaxDynamicSharedMemorySize, kQkvSmem);
    cudaFuncSetAttribute(attn_flash, cudaFuncAttributeMaxDynamicSharedMemorySize, kAttnSmem);

    prep_w<<<72, 512>>>(Wq, Wk, Wv);
    qkv_mma<<<(Bb * Tt) / 128, 256, kQkvSmem>>>(x);
    vtrans<<<Bb, 256>>>();

    dim3 grid2(Tt / 128, Bb);
    attn_flash<<<grid2, 256, kAttnSmem>>>(out);
}

// round 15
// speedup vs baseline: 3.5024x; 3.5024x over previous
#include <cuda_runtime.h>
#include <cuda_fp16.h>
#include <stdint.h>
#include <math.h>

#define Bb 256
#define Tt 256
#define Cc 384
#define Hh 64

// Intermediates: fp16 projections (Q pre-scaled by C^-0.5), V also transposed.
__device__ __half  g_q[Bb * Tt * Hh];
__device__ __half  g_k[Bb * Tt * Hh];
__device__ __half  g_v[Bb * Tt * Hh];
__device__ __half  g_vT[Bb * Hh * Tt];          // [b][h][t]
__device__ uint32_t g_wt[12 * 24 * 32 * 4];     // fp16 B-frags: [ch][ntg24][lane32][ks0j0,ks0j1,ks1j0,ks1j1]

// ---------------- helpers ----------------
__device__ __forceinline__ uint32_t pkhalf2(float lo, float hi) {
    uint32_t d;
    asm("cvt.rn.f16x2.f32 %0, %1, %2;" : "=r"(d) : "f"(hi), "f"(lo));
    return d;
}
__device__ __forceinline__ uint32_t smaddr(const void* p) {
    return (uint32_t)__cvta_generic_to_shared(p);
}
__device__ __forceinline__ void cpa16(uint32_t d, const void* s) {
    asm volatile("cp.async.cg.shared.global [%0], [%1], 16;\n" :: "r"(d), "l"(s));
}
__device__ __forceinline__ void cp_commit() { asm volatile("cp.async.commit_group;\n"); }
__device__ __forceinline__ void cp_wait0()  { asm volatile("cp.async.wait_group 0;\n" ::: "memory"); }

// m16n8k16 fp16 mma, fp32 accum
__device__ __forceinline__ void mma16(float c[4], const uint32_t a[4], uint32_t b0, uint32_t b1) {
    asm volatile(
        "mma.sync.aligned.m16n8k16.row.col.f32.f16.f16.f32 "
        "{%0,%1,%2,%3},{%4,%5,%6,%7},{%8,%9},{%0,%1,%2,%3};\n"
        : "+f"(c[0]), "+f"(c[1]), "+f"(c[2]), "+f"(c[3])
        : "r"(a[0]), "r"(a[1]), "r"(a[2]), "r"(a[3]), "r"(b0), "r"(b1));
}

// ---------------------------------------------------------------------------
// Kernel 0: weights -> fp16 B-fragments packed for LDS.128 (validated in R12).
//   g_wt[((ch*24+ntg)*32+lane)*4 + (ks*2+j)] = half2(W[k][n], W[k+1][n]),
//   n = ntg*8+gid, k = ch*32 + ks*16 + 2*tig + 8*j.
// ---------------------------------------------------------------------------
__global__ __launch_bounds__(512) void prep_w(
    const float* __restrict__ Wq, const float* __restrict__ Wk, const float* __restrict__ Wv)
{
    int idx = blockIdx.x * 512 + threadIdx.x;   // 72 blocks -> 36864
    int q    = idx & 3;
    int lane = (idx >> 2) & 31;
    int t    = idx >> 7;
    int ntg  = t % 24, ch = t / 24;
    int ks   = q >> 1, j = q & 1;
    int gid  = lane >> 2, tig = lane & 3;

    int n = ntg * 8 + gid;
    const float* W = (n < 64) ? Wq : (n < 128) ? Wk : Wv;
    int nc = n & 63;
    int k  = ch * 32 + ks * 16 + 2 * tig + 8 * j;

    g_wt[idx] = pkhalf2(W[k * Hh + nc], W[(k + 1) * Hh + nc]);
}

// ---------------------------------------------------------------------------
// Kernel 1: fused QKV projection, fp16 m16n8k16 (R11 structure; B via LDS.128).
//   256 threads = 8 warps (4m x 2n), warp tile 32x96, block 128x192,
//   K-chunk 32 (2 k16 steps), double-buffered cp.async. 2 CTA/SM (reg-limited).
// Smem: Xs 2*128*36 fp32 (raw x) | Wb 2*3072 u32 fragments = 61440 B
// ---------------------------------------------------------------------------
__global__ __launch_bounds__(256, 2) void qkv_mma(const float* __restrict__ x)
{
    extern __shared__ uint32_t sm[];
    float*    Xs = (float*)sm;            // 2 * 128*36
    uint32_t* Wb = sm + 2 * 128 * 36;     // 2 * 3072

    const int tid  = threadIdx.x;
    const int lane = tid & 31;
    const int wid  = tid >> 5;
    const int gid  = lane >> 2;
    const int tig  = lane & 3;
    const int wm   = wid & 3;           // rows wm*32
    const int wn   = wid >> 2;          // cols wn*96
    const int row0 = blockIdx.x * 128;

    auto issue = [&](int ch) {
        float*    Xb = Xs + (ch & 1) * (128 * 36);
        uint32_t* Bq = Wb + (ch & 1) * 3072;
        int kk = ch * 32;
        #pragma unroll
        for (int i = 0; i < 4; i++) {
            int idx = tid + i * 256;
            int r = idx >> 3, c4 = (idx & 7) * 4;
            cpa16(smaddr(&Xb[r * 36 + c4]), &x[(size_t)(row0 + r) * Cc + kk + c4]);
        }
        #pragma unroll
        for (int i = 0; i < 3; i++) {
            int idx = tid + i * 256;    // 768 granules of 16B
            cpa16(smaddr(&Bq[idx * 4]), &g_wt[(size_t)ch * 3072 + idx * 4]);
        }
        cp_commit();
    };

    float acc[2][12][4] = {};
    issue(0);

    for (int ch = 0; ch < 12; ch++) {
        cp_wait0();
        __syncthreads();
        if (ch < 11) issue(ch + 1);

        const float*    Xb = Xs + (ch & 1) * (128 * 36);
        const uint32_t* Bq = Wb + (ch & 1) * 3072;

        // A fragments for both k16 steps (fp32 -> fp16 pack in registers)
        uint32_t a[2][2][4];
        #pragma unroll
        for (int mt = 0; mt < 2; mt++) {
            int r = wm * 32 + mt * 16;
            #pragma unroll
            for (int ks = 0; ks < 2; ks++) {
                float2 v0 = *(const float2*)&Xb[(r + gid) * 36 + ks * 16 + 2 * tig];
                float2 v1 = *(const float2*)&Xb[(r + gid + 8) * 36 + ks * 16 + 2 * tig];
                float2 v2 = *(const float2*)&Xb[(r + gid) * 36 + ks * 16 + 2 * tig + 8];
                float2 v3 = *(const float2*)&Xb[(r + gid + 8) * 36 + ks * 16 + 2 * tig + 8];
                a[mt][ks][0] = pkhalf2(v0.x, v0.y);
                a[mt][ks][1] = pkhalf2(v1.x, v1.y);
                a[mt][ks][2] = pkhalf2(v2.x, v2.y);
                a[mt][ks][3] = pkhalf2(v3.x, v3.y);
            }
        }

        // B fragments: one LDS.128 per n-tile serves both k-steps
        #pragma unroll
        for (int t = 0; t < 12; t++) {
            uint4 Bv = *(const uint4*)&Bq[((wn * 12 + t) * 32 + lane) * 4];
            #pragma unroll
            for (int mt = 0; mt < 2; mt++) {
                mma16(acc[mt][t], a[mt][0], Bv.x, Bv.y);
                mma16(acc[mt][t], a[mt][1], Bv.z, Bv.w);
            }
        }
    }

    // Epilogue: fp16 stores; Q pre-scaled by C^-0.5
    const float scale = rsqrtf((float)Cc);
    #pragma unroll
    for (int mt = 0; mt < 2; mt++) {
        #pragma unroll
        for (int ntl = 0; ntl < 12; ntl++) {
            int n = wn * 96 + ntl * 8 + tig * 2;
            __half* outp = (n < 64) ? g_q : (n < 128) ? g_k : g_v;
            float sc = (n < 64) ? scale : 1.0f;
            int ncu = (n & 63) >> 1;
            int r = row0 + wm * 32 + mt * 16 + gid;
            ((uint32_t*)outp)[r * 32 + ncu] =
                pkhalf2(acc[mt][ntl][0] * sc, acc[mt][ntl][1] * sc);
            ((uint32_t*)outp)[(r + 8) * 32 + ncu] =
                pkhalf2(acc[mt][ntl][2] * sc, acc[mt][ntl][3] * sc);
        }
    }
}

// ---------------------------------------------------------------------------
// Kernel 1b: transpose V per batch: g_v[b][t][h] -> g_vT[b][h][t].
// ---------------------------------------------------------------------------
__global__ __launch_bounds__(256) void vtrans()
{
    __shared__ __half ts[64][260];
    const int b = blockIdx.x;
    const int tid = threadIdx.x;

    #pragma unroll
    for (int i = 0; i < 32; i++) {
        int idx = tid + i * 256;          // 8192 u32 of g_v slice
        int tok = idx >> 5, hp = idx & 31;
        uint32_t v = ((const uint32_t*)g_v)[(size_t)(b * Tt + tok) * 32 + hp];
        ts[hp * 2 + 0][tok] = __ushort_as_half((unsigned short)(v & 0xFFFF));
        ts[hp * 2 + 1][tok] = __ushort_as_half((unsigned short)(v >> 16));
    }
    __syncthreads();
    #pragma unroll
    for (int i = 0; i < 32; i++) {
        int idx = tid + i * 256;
        int h = idx >> 7, tp = idx & 127;
        ((uint32_t*)g_vT)[(size_t)(b * Hh + h) * 128 + tp] = *(uint32_t*)&ts[h][tp * 2];
    }
}

// ---------------------------------------------------------------------------
// Kernel 2: flash-attention, fp16 m16n8k16 (exact R11 winner, (256,2)).
// Smem (u32): Q 128*36 | K 2*64*36 | VT 2*64*36 = 55296 B
// ---------------------------------------------------------------------------
__global__ __launch_bounds__(256, 2) void attn_flash(float* __restrict__ out)
{
    extern __shared__ uint32_t sm[];
    uint32_t* Qs = sm;                 // 128*36
    uint32_t* Kb = sm + 128 * 36;      // 2 * 64*36
    uint32_t* Vb = Kb + 2 * 64 * 36;   // 2 * 64*36

    const int tid  = threadIdx.x;
    const int lane = tid & 31;
    const int wid  = tid >> 5;
    const int gid  = lane >> 2;
    const int tig  = lane & 3;
    const int qt   = 1 - blockIdx.x;    // heavy blocks first
    const int b    = blockIdx.y;
    const int q0   = qt * 128;
    const int r0   = wid * 16;
    const int lastT = 2 * qt + 1;
    const int dtile = (q0 + r0) >> 6;

    // Prologue: Q + K0 + V0
    #pragma unroll
    for (int i = 0; i < 4; i++) {
        int idx = tid + i * 256;
        int r = idx >> 3, gq = (idx & 7) * 4;
        cpa16(smaddr(&Qs[r * 36 + gq]), &g_q[(size_t)(b * Tt + q0 + r) * Hh + gq * 2]);
    }
    #pragma unroll
    for (int i = 0; i < 2; i++) {
        int idx = tid + i * 256;
        int r = idx >> 3, gq = (idx & 7) * 4;
        cpa16(smaddr(&Kb[r * 36 + gq]), &g_k[(size_t)(b * Tt + r) * Hh + gq * 2]);
        cpa16(smaddr(&Vb[r * 36 + gq]), &g_vT[(size_t)(b * Hh + r) * Tt + gq * 2]);
    }
    cp_commit();
    cp_wait0();
    __syncthreads();

    // Q fragments -> registers (16 u32)
    uint32_t Qa[4][4];
    #pragma unroll
    for (int ks = 0; ks < 4; ks++) {
        Qa[ks][0] = Qs[(r0 + gid) * 36 + 8 * ks + tig];
        Qa[ks][1] = Qs[(r0 + gid + 8) * 36 + 8 * ks + tig];
        Qa[ks][2] = Qs[(r0 + gid) * 36 + 8 * ks + tig + 4];
        Qa[ks][3] = Qs[(r0 + gid + 8) * 36 + 8 * ks + tig + 4];
    }

    float o[8][4] = {};
    float m0 = -1e30f, m1 = -1e30f, l0 = 0.f, l1 = 0.f;

    for (int jt = 0; jt <= lastT; jt++) {
        if (jt < lastT) {
            uint32_t* Kn = Kb + ((jt + 1) & 1) * (64 * 36);
            uint32_t* Vn = Vb + ((jt + 1) & 1) * (64 * 36);
            #pragma unroll
            for (int i = 0; i < 2; i++) {
                int idx = tid + i * 256;
                int r = idx >> 3, gq = (idx & 7) * 4;
                cpa16(smaddr(&Kn[r * 36 + gq]),
                      &g_k[(size_t)(b * Tt + (jt + 1) * 64 + r) * Hh + gq * 2]);
                cpa16(smaddr(&Vn[r * 36 + gq]),
                      &g_vT[(size_t)(b * Hh + r) * Tt + (jt + 1) * 64 + gq * 2]);
            }
            cp_commit();
        }

        if (jt <= dtile) {
            const uint32_t* K = Kb + (jt & 1) * (64 * 36);
            const uint32_t* V = Vb + (jt & 1) * (64 * 36);

            // ---- S = Q K^T : 16 rows x 64 keys ----
            float c4[8][4] = {};
            #pragma unroll
            for (int ks = 0; ks < 4; ks++) {
                #pragma unroll
                for (int nt = 0; nt < 8; nt++) {
                    int n = nt * 8 + gid;
                    uint32_t b0 = K[n * 36 + 8 * ks + tig];
                    uint32_t b1 = K[n * 36 + 8 * ks + tig + 4];
                    mma16(c4[nt], Qa[ks], b0, b1);
                }
            }

            if (jt == dtile) {
                int qg0 = q0 + r0 + gid, qg1 = qg0 + 8;
                #pragma unroll
                for (int nt = 0; nt < 8; nt++) {
                    int kg = jt * 64 + nt * 8 + tig * 2;
                    if (kg     > qg0) c4[nt][0] = -1e30f;
                    if (kg + 1 > qg0) c4[nt][1] = -1e30f;
                    if (kg     > qg1) c4[nt][2] = -1e30f;
                    if (kg + 1 > qg1) c4[nt][3] = -1e30f;
                }
            }

            // ---- online softmax ----
            float mx0 = -1e30f, mx1 = -1e30f;
            #pragma unroll
            for (int nt = 0; nt < 8; nt++) {
                mx0 = fmaxf(mx0, fmaxf(c4[nt][0], c4[nt][1]));
                mx1 = fmaxf(mx1, fmaxf(c4[nt][2], c4[nt][3]));
            }
            mx0 = fmaxf(mx0, __shfl_xor_sync(0xffffffffu, mx0, 1));
            mx0 = fmaxf(mx0, __shfl_xor_sync(0xffffffffu, mx0, 2));
            mx1 = fmaxf(mx1, __shfl_xor_sync(0xffffffffu, mx1, 1));
            mx1 = fmaxf(mx1, __shfl_xor_sync(0xffffffffu, mx1, 2));

            float m0n = fmaxf(m0, mx0), m1n = fmaxf(m1, mx1);
            float a0 = __expf(m0 - m0n), a1 = __expf(m1 - m1n);
            m0 = m0n; m1 = m1n;

            float s0 = 0.f, s1 = 0.f;
            #pragma unroll
            for (int nt = 0; nt < 8; nt++) {
                c4[nt][0] = __expf(c4[nt][0] - m0n);
                c4[nt][1] = __expf(c4[nt][1] - m0n);
                c4[nt][2] = __expf(c4[nt][2] - m1n);
                c4[nt][3] = __expf(c4[nt][3] - m1n);
                s0 += c4[nt][0] + c4[nt][1];
                s1 += c4[nt][2] + c4[nt][3];
            }
            s0 += __shfl_xor_sync(0xffffffffu, s0, 1);
            s0 += __shfl_xor_sync(0xffffffffu, s0, 2);
            s1 += __shfl_xor_sync(0xffffffffu, s1, 1);
            s1 += __shfl_xor_sync(0xffffffffu, s1, 2);
            l0 = l0 * a0 + s0;
            l1 = l1 * a1 + s1;

            #pragma unroll
            for (int nt = 0; nt < 8; nt++) {
                o[nt][0] *= a0; o[nt][1] *= a0;
                o[nt][2] *= a1; o[nt][3] *= a1;
            }

            // ---- O += P V : P packs straight into A fragments ----
            #pragma unroll
            for (int j = 0; j < 4; j++) {
                uint32_t a[4];
                a[0] = pkhalf2(c4[2 * j][0],     c4[2 * j][1]);
                a[1] = pkhalf2(c4[2 * j][2],     c4[2 * j][3]);
                a[2] = pkhalf2(c4[2 * j + 1][0], c4[2 * j + 1][1]);
                a[3] = pkhalf2(c4[2 * j + 1][2], c4[2 * j + 1][3]);
                #pragma unroll
                for (int nt = 0; nt < 8; nt++) {
                    int n = nt * 8 + gid;                  // h column
                    uint32_t b0 = V[n * 36 + 8 * j + tig];
                    uint32_t b1 = V[n * 36 + 8 * j + tig + 4];
                    mma16(o[nt], a, b0, b1);
                }
            }
        }

        if (jt < lastT) {
            cp_wait0();
            __syncthreads();
        }
    }

    // ---- normalize and store fp32 ----
    float i0 = 1.f / l0, i1 = 1.f / l1;
    int row = b * Tt + q0 + r0 + gid;
    #pragma unroll
    for (int nt = 0; nt < 8; nt++) {
        int col = nt * 8 + tig * 2;
        *(float2*)&out[(size_t)row * Hh + col]       = make_float2(o[nt][0] * i0, o[nt][1] * i0);
        *(float2*)&out[(size_t)(row + 8) * Hh + col] = make_float2(o[nt][2] * i1, o[nt][3] * i1);
    }
}

// ---------------------------------------------------------------------------
extern "C" void kernel_launch(void* const* d_in, const int* in_sizes, int n_in,
                              void* d_out, int out_size)
{
    const float* x  = (const float*)d_in[0];
    const float* Wq = (const float*)d_in[1];
    const float* Wk = (const float*)d_in[2];
    const float* Wv = (const float*)d_in[3];
    float* out = (float*)d_out;

    static const int kQkvSmem  = (2 * 128 * 36 + 2 * 3072) * (int)sizeof(uint32_t);   // 61440
    static const int kAttnSmem = (128 * 36 + 4 * 64 * 36) * (int)sizeof(uint32_t);    // 55296
    cudaFuncSetAttribute(qkv_mma, cudaFuncAttributeMaxDynamicSharedMemorySize, kQkvSmem);
    cudaFuncSetAttribute(attn_flash, cudaFuncAttributeMaxDynamicSharedMemorySize, kAttnSmem);

    prep_w<<<72, 512>>>(Wq, Wk, Wv);
    qkv_mma<<<(Bb * Tt) / 128, 256, kQkvSmem>>>(x);
    vtrans<<<Bb, 256>>>();

    dim3 grid2(Tt / 128, Bb);
    attn_flash<<<grid2, 256, kAttnSmem>>>(out);
}

// round 16
// speedup vs baseline: 3.9452x; 1.1264x over previous
#include <cuda_runtime.h>
#include <cuda_fp16.h>
#include <stdint.h>
#include <math.h>

#define Bb 256
#define Tt 256
#define Cc 384
#define Hh 64

// Intermediates: fp16 projections. Q pre-scaled by C^-0.5 * log2(e).
// V written directly in transposed layout g_vT[b][h][t] by qkv's epilogue.
__device__ __half  g_q[Bb * Tt * Hh];
__device__ __half  g_k[Bb * Tt * Hh];
__device__ __half  g_vT[Bb * Hh * Tt];          // [b][h][t]
__device__ uint32_t g_wt[12 * 3072];            // fp16 B-fragments: [ch][ntg24][ks2][lane32][j2]

// ---------------- helpers ----------------
__device__ __forceinline__ uint32_t pkhalf2(float lo, float hi) {
    uint32_t d;
    asm("cvt.rn.f16x2.f32 %0, %1, %2;" : "=r"(d) : "f"(hi), "f"(lo));
    return d;
}
__device__ __forceinline__ float ex2(float x) {
    float r;
    asm("ex2.approx.ftz.f32 %0, %1;" : "=f"(r) : "f"(x));
    return r;
}
__device__ __forceinline__ uint32_t smaddr(const void* p) {
    return (uint32_t)__cvta_generic_to_shared(p);
}
__device__ __forceinline__ void cpa16(uint32_t d, const void* s) {
    asm volatile("cp.async.cg.shared.global [%0], [%1], 16;\n" :: "r"(d), "l"(s));
}
__device__ __forceinline__ void cp_commit() { asm volatile("cp.async.commit_group;\n"); }
__device__ __forceinline__ void cp_wait0()  { asm volatile("cp.async.wait_group 0;\n" ::: "memory"); }

// m16n8k16 fp16 mma, fp32 accum
__device__ __forceinline__ void mma16(float c[4], const uint32_t a[4], uint32_t b0, uint32_t b1) {
    asm volatile(
        "mma.sync.aligned.m16n8k16.row.col.f32.f16.f16.f32 "
        "{%0,%1,%2,%3},{%4,%5,%6,%7},{%8,%9},{%0,%1,%2,%3};\n"
        : "+f"(c[0]), "+f"(c[1]), "+f"(c[2]), "+f"(c[3])
        : "r"(a[0]), "r"(a[1]), "r"(a[2]), "r"(a[3]), "r"(b0), "r"(b1));
}

// ---------------------------------------------------------------------------
// Kernel 0: weights -> fp16 B-fragments (exact R11 layout).
//   g_wt[(((ch*24+ntg)*2+ks)*32+lane)*2+j] = half2(W[k][n], W[k+1][n]),
//   n = ntg*8+gid, k = ch*32 + ks*16 + 2*tig + 8*j.
// ---------------------------------------------------------------------------
__global__ __launch_bounds__(512) void prep_w(
    const float* __restrict__ Wq, const float* __restrict__ Wk, const float* __restrict__ Wv)
{
    int idx = blockIdx.x * 512 + threadIdx.x;   // 72 blocks -> 36864
    int j    = idx & 1;
    int lane = (idx >> 1) & 31;
    int ks   = (idx >> 6) & 1;
    int t    = idx >> 7;
    int ntg  = t % 24, ch = t / 24;
    int gid  = lane >> 2, tig = lane & 3;

    int n = ntg * 8 + gid;
    const float* W = (n < 64) ? Wq : (n < 128) ? Wk : Wv;
    int nc = n & 63;
    int k  = ch * 32 + ks * 16 + 2 * tig + 8 * j;

    g_wt[idx] = pkhalf2(W[k * Hh + nc], W[(k + 1) * Hh + nc]);
}

// ---------------------------------------------------------------------------
// Kernel 1: fused QKV projection, fp16 m16n8k16 (exact R11 inner loop).
//   256 threads = 8 warps (4m x 2n), warp tile 32x96, block 128x192,
//   K-chunk 32, double-buffered cp.async. V written transposed to g_vT.
// Smem: Xs 2*128*36 fp32 (raw x) | Wb 2*3072 u32 fragments = 61440 B
// ---------------------------------------------------------------------------
__global__ __launch_bounds__(256, 2) void qkv_mma(const float* __restrict__ x)
{
    extern __shared__ uint32_t sm[];
    float*    Xs = (float*)sm;            // 2 * 128*36
    uint32_t* Wb = sm + 2 * 128 * 36;     // 2 * 3072

    const int tid  = threadIdx.x;
    const int lane = tid & 31;
    const int wid  = tid >> 5;
    const int gid  = lane >> 2;
    const int tig  = lane & 3;
    const int wm   = wid & 3;           // rows wm*32
    const int wn   = wid >> 2;          // cols wn*96
    const int row0 = blockIdx.x * 128;

    auto issue = [&](int ch) {
        float*    Xb = Xs + (ch & 1) * (128 * 36);
        uint32_t* Bq = Wb + (ch & 1) * 3072;
        int kk = ch * 32;
        #pragma unroll
        for (int i = 0; i < 4; i++) {
            int idx = tid + i * 256;
            int r = idx >> 3, c4 = (idx & 7) * 4;
            cpa16(smaddr(&Xb[r * 36 + c4]), &x[(size_t)(row0 + r) * Cc + kk + c4]);
        }
        #pragma unroll
        for (int i = 0; i < 3; i++) {
            int idx = tid + i * 256;    // 768 granules of 16B
            cpa16(smaddr(&Bq[idx * 4]), &g_wt[(size_t)ch * 3072 + idx * 4]);
        }
        cp_commit();
    };

    float acc[2][12][4] = {};
    issue(0);

    for (int ch = 0; ch < 12; ch++) {
        cp_wait0();
        __syncthreads();
        if (ch < 11) issue(ch + 1);

        const float*    Xb = Xs + (ch & 1) * (128 * 36);
        const uint32_t* Bq = Wb + (ch & 1) * 3072;

        #pragma unroll
        for (int ks = 0; ks < 2; ks++) {
            // A fragments (fp32 -> fp16 pack in registers)
            uint32_t a[2][4];
            #pragma unroll
            for (int mt = 0; mt < 2; mt++) {
                int r = wm * 32 + mt * 16;
                float2 v0 = *(const float2*)&Xb[(r + gid) * 36 + ks * 16 + 2 * tig];
                float2 v1 = *(const float2*)&Xb[(r + gid + 8) * 36 + ks * 16 + 2 * tig];
                float2 v2 = *(const float2*)&Xb[(r + gid) * 36 + ks * 16 + 2 * tig + 8];
                float2 v3 = *(const float2*)&Xb[(r + gid + 8) * 36 + ks * 16 + 2 * tig + 8];
                a[mt][0] = pkhalf2(v0.x, v0.y);
                a[mt][1] = pkhalf2(v1.x, v1.y);
                a[mt][2] = pkhalf2(v2.x, v2.y);
                a[mt][3] = pkhalf2(v3.x, v3.y);
            }
            // B fragments, 2 halves of 6 n-tiles
            #pragma unroll
            for (int h = 0; h < 2; h++) {
                uint2 Bv[6];
                #pragma unroll
                for (int t = 0; t < 6; t++) {
                    int ntl = h * 6 + t;
                    Bv[t] = *(const uint2*)&Bq[(((wn * 12 + ntl) * 2 + ks) * 32 + lane) * 2];
                }
                #pragma unroll
                for (int mt = 0; mt < 2; mt++)
                    #pragma unroll
                    for (int t = 0; t < 6; t++)
                        mma16(acc[mt][h * 6 + t], a[mt], Bv[t].x, Bv[t].y);
            }
        }
    }

    // Epilogue. Q pre-scaled by C^-0.5 * log2(e) (softmax uses ex2).
    // V columns (n>=128) written transposed directly to g_vT[b][h][t].
    const float scale = rsqrtf((float)Cc) * 1.4426950408889634f;
    const int bB = blockIdx.x >> 1;            // batch of this 128-row tile
    const int t0 = (blockIdx.x & 1) * 128;     // token base within batch
    #pragma unroll
    for (int mt = 0; mt < 2; mt++) {
        #pragma unroll
        for (int ntl = 0; ntl < 12; ntl++) {
            int n = wn * 96 + ntl * 8 + tig * 2;
            int rl = wm * 32 + mt * 16 + gid;
            if (n < 128) {
                __half* outp = (n < 64) ? g_q : g_k;
                float sc = (n < 64) ? scale : 1.0f;
                int ncu = (n & 63) >> 1;
                int r = row0 + rl;
                ((uint32_t*)outp)[r * 32 + ncu] =
                    pkhalf2(acc[mt][ntl][0] * sc, acc[mt][ntl][1] * sc);
                ((uint32_t*)outp)[(r + 8) * 32 + ncu] =
                    pkhalf2(acc[mt][ntl][2] * sc, acc[mt][ntl][3] * sc);
            } else {
                int h = n - 128;
                int t = t0 + rl;
                __half* vt = g_vT + (size_t)bB * Hh * Tt;
                vt[h * Tt + t]           = __float2half(acc[mt][ntl][0]);
                vt[(h + 1) * Tt + t]     = __float2half(acc[mt][ntl][1]);
                vt[h * Tt + t + 8]       = __float2half(acc[mt][ntl][2]);
                vt[(h + 1) * Tt + t + 8] = __float2half(acc[mt][ntl][3]);
            }
        }
    }
}

// ---------------------------------------------------------------------------
// Kernel 2: flash-attention, fp16 m16n8k16 (R11 winner; exp -> ex2).
// Smem (u32): Q 128*36 | K 2*64*36 | VT 2*64*36 = 55296 B
// ---------------------------------------------------------------------------
__global__ __launch_bounds__(256, 2) void attn_flash(float* __restrict__ out)
{
    extern __shared__ uint32_t sm[];
    uint32_t* Qs = sm;                 // 128*36
    uint32_t* Kb = sm + 128 * 36;      // 2 * 64*36
    uint32_t* Vb = Kb + 2 * 64 * 36;   // 2 * 64*36

    const int tid  = threadIdx.x;
    const int lane = tid & 31;
    const int wid  = tid >> 5;
    const int gid  = lane >> 2;
    const int tig  = lane & 3;
    const int qt   = 1 - blockIdx.x;    // heavy blocks first
    const int b    = blockIdx.y;
    const int q0   = qt * 128;
    const int r0   = wid * 16;
    const int lastT = 2 * qt + 1;
    const int dtile = (q0 + r0) >> 6;

    // Prologue: Q + K0 + V0
    #pragma unroll
    for (int i = 0; i < 4; i++) {
        int idx = tid + i * 256;
        int r = idx >> 3, gq = (idx & 7) * 4;
        cpa16(smaddr(&Qs[r * 36 + gq]), &g_q[(size_t)(b * Tt + q0 + r) * Hh + gq * 2]);
    }
    #pragma unroll
    for (int i = 0; i < 2; i++) {
        int idx = tid + i * 256;
        int r = idx >> 3, gq = (idx & 7) * 4;
        cpa16(smaddr(&Kb[r * 36 + gq]), &g_k[(size_t)(b * Tt + r) * Hh + gq * 2]);
        cpa16(smaddr(&Vb[r * 36 + gq]), &g_vT[(size_t)(b * Hh + r) * Tt + gq * 2]);
    }
    cp_commit();
    cp_wait0();
    __syncthreads();

    // Q fragments -> registers (16 u32)
    uint32_t Qa[4][4];
    #pragma unroll
    for (int ks = 0; ks < 4; ks++) {
        Qa[ks][0] = Qs[(r0 + gid) * 36 + 8 * ks + tig];
        Qa[ks][1] = Qs[(r0 + gid + 8) * 36 + 8 * ks + tig];
        Qa[ks][2] = Qs[(r0 + gid) * 36 + 8 * ks + tig + 4];
        Qa[ks][3] = Qs[(r0 + gid + 8) * 36 + 8 * ks + tig + 4];
    }

    float o[8][4] = {};
    float m0 = -1e30f, m1 = -1e30f, l0 = 0.f, l1 = 0.f;

    for (int jt = 0; jt <= lastT; jt++) {
        if (jt < lastT) {
            uint32_t* Kn = Kb + ((jt + 1) & 1) * (64 * 36);
            uint32_t* Vn = Vb + ((jt + 1) & 1) * (64 * 36);
            #pragma unroll
            for (int i = 0; i < 2; i++) {
                int idx = tid + i * 256;
                int r = idx >> 3, gq = (idx & 7) * 4;
                cpa16(smaddr(&Kn[r * 36 + gq]),
                      &g_k[(size_t)(b * Tt + (jt + 1) * 64 + r) * Hh + gq * 2]);
                cpa16(smaddr(&Vn[r * 36 + gq]),
                      &g_vT[(size_t)(b * Hh + r) * Tt + (jt + 1) * 64 + gq * 2]);
            }
            cp_commit();
        }

        if (jt <= dtile) {
            const uint32_t* K = Kb + (jt & 1) * (64 * 36);
            const uint32_t* V = Vb + (jt & 1) * (64 * 36);

            // ---- S = Q K^T : 16 rows x 64 keys (S already in log2 units) ----
            float c4[8][4] = {};
            #pragma unroll
            for (int ks = 0; ks < 4; ks++) {
                #pragma unroll
                for (int nt = 0; nt < 8; nt++) {
                    int n = nt * 8 + gid;
                    uint32_t b0 = K[n * 36 + 8 * ks + tig];
                    uint32_t b1 = K[n * 36 + 8 * ks + tig + 4];
                    mma16(c4[nt], Qa[ks], b0, b1);
                }
            }

            if (jt == dtile) {
                int qg0 = q0 + r0 + gid, qg1 = qg0 + 8;
                #pragma unroll
                for (int nt = 0; nt < 8; nt++) {
                    int kg = jt * 64 + nt * 8 + tig * 2;
                    if (kg     > qg0) c4[nt][0] = -1e30f;
                    if (kg + 1 > qg0) c4[nt][1] = -1e30f;
                    if (kg     > qg1) c4[nt][2] = -1e30f;
                    if (kg + 1 > qg1) c4[nt][3] = -1e30f;
                }
            }

            // ---- online softmax (base-2) ----
            float mx0 = -1e30f, mx1 = -1e30f;
            #pragma unroll
            for (int nt = 0; nt < 8; nt++) {
                mx0 = fmaxf(mx0, fmaxf(c4[nt][0], c4[nt][1]));
                mx1 = fmaxf(mx1, fmaxf(c4[nt][2], c4[nt][3]));
            }
            mx0 = fmaxf(mx0, __shfl_xor_sync(0xffffffffu, mx0, 1));
            mx0 = fmaxf(mx0, __shfl_xor_sync(0xffffffffu, mx0, 2));
            mx1 = fmaxf(mx1, __shfl_xor_sync(0xffffffffu, mx1, 1));
            mx1 = fmaxf(mx1, __shfl_xor_sync(0xffffffffu, mx1, 2));

            float m0n = fmaxf(m0, mx0), m1n = fmaxf(m1, mx1);
            float a0 = ex2(m0 - m0n), a1 = ex2(m1 - m1n);
            m0 = m0n; m1 = m1n;

            float s0 = 0.f, s1 = 0.f;
            #pragma unroll
            for (int nt = 0; nt < 8; nt++) {
                c4[nt][0] = ex2(c4[nt][0] - m0n);
                c4[nt][1] = ex2(c4[nt][1] - m0n);
                c4[nt][2] = ex2(c4[nt][2] - m1n);
                c4[nt][3] = ex2(c4[nt][3] - m1n);
                s0 += c4[nt][0] + c4[nt][1];
                s1 += c4[nt][2] + c4[nt][3];
            }
            s0 += __shfl_xor_sync(0xffffffffu, s0, 1);
            s0 += __shfl_xor_sync(0xffffffffu, s0, 2);
            s1 += __shfl_xor_sync(0xffffffffu, s1, 1);
            s1 += __shfl_xor_sync(0xffffffffu, s1, 2);
            l0 = l0 * a0 + s0;
            l1 = l1 * a1 + s1;

            #pragma unroll
            for (int nt = 0; nt < 8; nt++) {
                o[nt][0] *= a0; o[nt][1] *= a0;
                o[nt][2] *= a1; o[nt][3] *= a1;
            }

            // ---- O += P V : P packs straight into A fragments ----
            #pragma unroll
            for (int j = 0; j < 4; j++) {
                uint32_t a[4];
                a[0] = pkhalf2(c4[2 * j][0],     c4[2 * j][1]);
                a[1] = pkhalf2(c4[2 * j][2],     c4[2 * j][3]);
                a[2] = pkhalf2(c4[2 * j + 1][0], c4[2 * j + 1][1]);
                a[3] = pkhalf2(c4[2 * j + 1][2], c4[2 * j + 1][3]);
                #pragma unroll
                for (int nt = 0; nt < 8; nt++) {
                    int n = nt * 8 + gid;                  // h column
                    uint32_t b0 = V[n * 36 + 8 * j + tig];
                    uint32_t b1 = V[n * 36 + 8 * j + tig + 4];
                    mma16(o[nt], a, b0, b1);
                }
            }
        }

        if (jt < lastT) {
            cp_wait0();
            __syncthreads();
        }
    }

    // ---- normalize and store fp32 ----
    float i0 = 1.f / l0, i1 = 1.f / l1;
    int row = b * Tt + q0 + r0 + gid;
    #pragma unroll
    for (int nt = 0; nt < 8; nt++) {
        int col = nt * 8 + tig * 2;
        *(float2*)&out[(size_t)row * Hh + col]       = make_float2(o[nt][0] * i0, o[nt][1] * i0);
        *(float2*)&out[(size_t)(row + 8) * Hh + col] = make_float2(o[nt][2] * i1, o[nt][3] * i1);
    }
}

// ---------------------------------------------------------------------------
extern "C" void kernel_launch(void* const* d_in, const int* in_sizes, int n_in,
                              void* d_out, int out_size)
{
    const float* x  = (const float*)d_in[0];
    const float* Wq = (const float*)d_in[1];
    const float* Wk = (const float*)d_in[2];
    const float* Wv = (const float*)d_in[3];
    float* out = (float*)d_out;

    static const int kQkvSmem  = (2 * 128 * 36 + 2 * 3072) * (int)sizeof(uint32_t);   // 61440
    static const int kAttnSmem = (128 * 36 + 4 * 64 * 36) * (int)sizeof(uint32_t);    // 55296
    cudaFuncSetAttribute(qkv_mma, cudaFuncAttributeMaxDynamicSharedMemorySize, kQkvSmem);
    cudaFuncSetAttribute(attn_flash, cudaFuncAttributeMaxDynamicSharedMemorySize, kAttnSmem);

    prep_w<<<72, 512>>>(Wq, Wk, Wv);
    qkv_mma<<<(Bb * Tt) / 128, 256, kQkvSmem>>>(x);

    dim3 grid2(Tt / 128, Bb);
    attn_flash<<<grid2, 256, kAttnSmem>>>(out);
}